// round 12
// baseline (speedup 1.0000x reference)
#include <cuda_runtime.h>
#include <cuda_bf16.h>

// RepeatLayers: variable-length repeat_interleave along axis 0.
//   encoder_h: [N=8192, D=1024] fp32
//   repeats:   [N] int32 in [0, 8)
//   out:       [sum(repeats), D] fp32
//
// R12: fused single kernel, ROWS_PER_CTA=16 (grid 512 -> only 8.4MB redundant
// prefix reads), but register-lean: rows streamed in 4 groups of 4 with ONE
// group live at a time, offsets computed incrementally (no off[16] array).
// Target regs ~32 -> occ 8 (cross-round evidence: occupancy, not traffic,
// drives the scatter throughput).

#define N_ROWS 8192
#define D_ELEMS 1024
#define D_VEC4 (D_ELEMS / 4)     // 256 float4 per row
#define ROWS_PER_CTA 16
#define NB_CTAS (N_ROWS / ROWS_PER_CTA)   // 512

__global__ __launch_bounds__(256, 8)
void repeat_fused_kernel(const float* __restrict__ src,
                         const int* __restrict__ repeats,
                         float* __restrict__ out) {
    const int t = threadIdx.x;                    // 0..255
    const int lane = t & 31;
    const int wid = t >> 5;
    const int row0 = blockIdx.x * ROWS_PER_CTA;   // first of this CTA's 16 rows

    // --- Cooperative prefix sum: off0 = sum(repeats[0..row0)) ---
    const int n4 = row0 >> 2;       // 4*blockIdx.x int4 words
    const int4* rp = reinterpret_cast<const int4*>(repeats);
    int sum = 0;
    for (int i = t; i < n4; i += 256) {
        int4 a = __ldg(&rp[i]);
        sum += a.x + a.y + a.z + a.w;
    }
#pragma unroll
    for (int d = 16; d >= 1; d >>= 1) {
        sum += __shfl_xor_sync(0xFFFFFFFFu, sum, d);
    }

    __shared__ int wsum[8];
    if (lane == 0) wsum[wid] = sum;
    __syncthreads();
    if (wid == 0) {   // full warp active
        int s2 = (lane < 8) ? wsum[lane] : 0;
#pragma unroll
        for (int d = 16; d >= 1; d >>= 1) {
            s2 += __shfl_xor_sync(0xFFFFFFFFu, s2, d);
        }
        if (lane == 0) wsum[0] = s2;
    }
    __syncthreads();

    int cur = wsum[0];   // running output-row offset

    const float4* srcv = reinterpret_cast<const float4*>(src);
    float4* outv = reinterpret_cast<float4*>(out);

    // --- Stream 4 groups of 4 rows; one group of row data live at a time ---
#pragma unroll
    for (int g = 0; g < 4; g++) {
        const int gr = row0 + 4 * g;
        const int4 r4 = __ldg(reinterpret_cast<const int4*>(&repeats[gr]));
        const int rep[4] = {r4.x, r4.y, r4.z, r4.w};

        // Front-batch the 4 independent row loads of this group.
        float4 v[4];
#pragma unroll
        for (int i = 0; i < 4; i++) {
            if (rep[i] > 0) v[i] = __ldg(srcv + (size_t)(gr + i) * D_VEC4 + t);
        }

        // Store each row rep[i] times; advance the running offset.
#pragma unroll
        for (int i = 0; i < 4; i++) {
            float4* o = outv + (size_t)cur * D_VEC4 + t;
#pragma unroll 8
            for (int r = 0; r < rep[i]; r++) {
                *o = v[i];
                o += D_VEC4;
            }
            cur += rep[i];
        }
    }
}

extern "C" void kernel_launch(void* const* d_in, const int* in_sizes, int n_in,
                              void* d_out, int out_size) {
    const float* encoder_h;
    const int* repeats;
    if (in_sizes[0] == N_ROWS * D_ELEMS) {
        encoder_h = (const float*)d_in[0];
        repeats   = (const int*)d_in[1];
    } else {
        encoder_h = (const float*)d_in[1];
        repeats   = (const int*)d_in[0];
    }
    float* out = (float*)d_out;
    (void)n_in; (void)out_size;

    repeat_fused_kernel<<<NB_CTAS, 256>>>(encoder_h, repeats, out);
}

// round 13
// speedup vs baseline: 1.0146x; 1.0146x over previous
#include <cuda_runtime.h>
#include <cuda_bf16.h>

// RepeatLayers: variable-length repeat_interleave along axis 0.
//   encoder_h: [N=8192, D=1024] fp32
//   repeats:   [N] int32 in [0, 8)
//   out:       [sum(repeats), D] fp32
//
// R13 = R8 (best: fused single kernel, 8 rows/CTA, grid 1024, 4+4 row split)
// with the prefix critical path tightened:
//   - prefix-sum loads issued FIRST (they gate all stores),
//   - REDUX (__reduce_add_sync) replaces shuffle trees,
//   - plain float4 loads/stores (policy hints measured neutral).

#define N_ROWS 8192
#define D_ELEMS 1024
#define D_VEC4 (D_ELEMS / 4)     // 256 float4 per row
#define ROWS_PER_CTA 8
#define NB_CTAS (N_ROWS / ROWS_PER_CTA)   // 1024

__global__ __launch_bounds__(256, 6)
void repeat_fused_kernel(const float* __restrict__ src,
                         const int* __restrict__ repeats,
                         float* __restrict__ out) {
    const int t = threadIdx.x;                    // 0..255
    const int lane = t & 31;
    const int wid = t >> 5;
    const int row0 = blockIdx.x * ROWS_PER_CTA;   // first of this CTA's 8 rows

    // --- 1. Prefix-chain loads FIRST: sum = part of repeats[0..row0) ---
    const int n4 = row0 >> 2;                     // 2*blockIdx.x int4 words
    const int4* rp = reinterpret_cast<const int4*>(repeats);
    int sum = 0;
    for (int i = t; i < n4; i += 256) {
        int4 a = __ldg(&rp[i]);
        sum += a.x + a.y + a.z + a.w;
    }

    // --- 2. This CTA's 8 repeat counts ---
    const int4 ra = __ldg(&rp[2 * blockIdx.x]);
    const int4 rb = __ldg(&rp[2 * blockIdx.x + 1]);
    const int rep[ROWS_PER_CTA] = {ra.x, ra.y, ra.z, ra.w, rb.x, rb.y, rb.z, rb.w};

    // --- 3. Front-batch group A row loads (rows 0..3) ---
    const float4* srcv = reinterpret_cast<const float4*>(src);
    float4 va[4];
#pragma unroll
    for (int i = 0; i < 4; i++) {
        if (rep[i] > 0) va[i] = __ldg(srcv + (size_t)(row0 + i) * D_VEC4 + t);
    }

    // --- 4. Block reduction of the prefix partials (REDUX, short chain) ---
    sum = __reduce_add_sync(0xFFFFFFFFu, sum);

    __shared__ int wsum[8];
    if (lane == 0) wsum[wid] = sum;
    __syncthreads();
    int off0;
    {
        int s2 = (lane < 8) ? wsum[lane] : 0;     // every warp reduces locally;
        off0 = __reduce_add_sync(0xFFFFFFFFu, s2); // no second barrier needed
    }

    // Per-row output offsets.
    int off[ROWS_PER_CTA];
    off[0] = off0;
#pragma unroll
    for (int i = 1; i < ROWS_PER_CTA; i++) off[i] = off[i - 1] + rep[i - 1];

    float4* outv = reinterpret_cast<float4*>(out);

    // --- 5. Issue group B loads (rows 4..7) before draining group A stores ---
    float4 vb[4];
#pragma unroll
    for (int i = 0; i < 4; i++) {
        if (rep[4 + i] > 0) vb[i] = __ldg(srcv + (size_t)(row0 + 4 + i) * D_VEC4 + t);
    }

    // --- 6. Store group A ---
#pragma unroll
    for (int i = 0; i < 4; i++) {
        float4* o = outv + (size_t)off[i] * D_VEC4 + t;
#pragma unroll 8
        for (int r = 0; r < rep[i]; r++) { *o = va[i]; o += D_VEC4; }
    }

    // --- 7. Store group B ---
#pragma unroll
    for (int i = 0; i < 4; i++) {
        float4* o = outv + (size_t)off[4 + i] * D_VEC4 + t;
#pragma unroll 8
        for (int r = 0; r < rep[4 + i]; r++) { *o = vb[i]; o += D_VEC4; }
    }
}

extern "C" void kernel_launch(void* const* d_in, const int* in_sizes, int n_in,
                              void* d_out, int out_size) {
    const float* encoder_h;
    const int* repeats;
    if (in_sizes[0] == N_ROWS * D_ELEMS) {
        encoder_h = (const float*)d_in[0];
        repeats   = (const int*)d_in[1];
    } else {
        encoder_h = (const float*)d_in[1];
        repeats   = (const int*)d_in[0];
    }
    float* out = (float*)d_out;
    (void)n_in; (void)out_size;

    repeat_fused_kernel<<<NB_CTAS, 256>>>(encoder_h, repeats, out);
}

// round 14
// speedup vs baseline: 1.2485x; 1.2305x over previous
#include <cuda_runtime.h>
#include <cuda_bf16.h>

// RepeatLayers: variable-length repeat_interleave along axis 0.
//   encoder_h: [N=8192, D=1024] fp32
//   repeats:   [N] int32 in [0, 8)
//   out:       [sum(repeats), D] fp32
//
// R14 = EXACT R8 (best: 26.8us total / 25.2us kernel) + ONE delta:
// both shuffle reduction trees replaced by __reduce_add_sync (REDUX.SUM),
// dropping the second __syncthreads. Everything else — load ordering
// (reps -> group-A rows -> prefix -> reduce -> group-B rows -> stores),
// L2 evict hints, RPC=8, grid 1024, launch_bounds(256,6) — unchanged.

#define N_ROWS 8192
#define D_ELEMS 1024
#define D_VEC4 (D_ELEMS / 4)     // 256 float4 per row
#define ROWS_PER_CTA 8
#define NB_CTAS (N_ROWS / ROWS_PER_CTA)   // 1024

// ---- L2 policy helpers (as in R8) ----
__device__ __forceinline__ float4 ldg_evict_last(const float4* p) {
    float4 v;
    asm volatile(
        "{\n\t"
        ".reg .b64 pol;\n\t"
        "createpolicy.fractional.L2::evict_last.b64 pol, 1.0;\n\t"
        "ld.global.nc.L2::cache_hint.v4.f32 {%0,%1,%2,%3}, [%4], pol;\n\t"
        "}"
        : "=f"(v.x), "=f"(v.y), "=f"(v.z), "=f"(v.w) : "l"(p));
    return v;
}
__device__ __forceinline__ void stg_evict_first(float4* p, float4 v) {
    asm volatile(
        "{\n\t"
        ".reg .b64 pol;\n\t"
        "createpolicy.fractional.L2::evict_first.b64 pol, 1.0;\n\t"
        "st.global.L2::cache_hint.v4.f32 [%0], {%1,%2,%3,%4}, pol;\n\t"
        "}"
        :: "l"(p), "f"(v.x), "f"(v.y), "f"(v.z), "f"(v.w) : "memory");
}

__global__ __launch_bounds__(256, 6)
void repeat_fused_kernel(const float* __restrict__ src,
                         const int* __restrict__ repeats,
                         float* __restrict__ out) {
    const int t = threadIdx.x;                    // 0..255
    const int lane = t & 31;
    const int wid = t >> 5;
    const int row0 = blockIdx.x * ROWS_PER_CTA;   // first of this CTA's 8 rows

    // --- This CTA's 8 repeat counts (two int4) ---
    const int4 ra = __ldg(reinterpret_cast<const int4*>(&repeats[row0]));
    const int4 rb = __ldg(reinterpret_cast<const int4*>(&repeats[row0 + 4]));
    const int rep[ROWS_PER_CTA] = {ra.x, ra.y, ra.z, ra.w, rb.x, rb.y, rb.z, rb.w};

    // --- Front-batch group A row loads (rows 0..3), evict_last ---
    const float4* srcv = reinterpret_cast<const float4*>(src);
    float4 va[4];
#pragma unroll
    for (int i = 0; i < 4; i++) {
        if (rep[i] > 0) va[i] = ldg_evict_last(srcv + (size_t)(row0 + i) * D_VEC4 + t);
    }

    // --- Cooperative prefix sum: off0 = sum(repeats[0..row0)) ---
    const int n4 = row0 >> 2;                       // 2*blockIdx.x int4 words
    const int4* rp = reinterpret_cast<const int4*>(repeats);
    int sum = 0;
    for (int i = t; i < n4; i += 256) {
        int4 a = __ldg(&rp[i]);
        sum += a.x + a.y + a.z + a.w;
    }
    // REDUX: single-instruction warp reduction (delta vs R8).
    sum = __reduce_add_sync(0xFFFFFFFFu, sum);

    __shared__ int wsum[8];
    if (lane == 0) wsum[wid] = sum;
    __syncthreads();
    // Every warp reduces the 8 warp totals locally — no second barrier.
    int off0;
    {
        int s2 = (lane < 8) ? wsum[lane] : 0;
        off0 = __reduce_add_sync(0xFFFFFFFFu, s2);
    }

    // Per-row output offsets.
    int off[ROWS_PER_CTA];
    off[0] = off0;
#pragma unroll
    for (int i = 1; i < ROWS_PER_CTA; i++) off[i] = off[i - 1] + rep[i - 1];

    float4* outv = reinterpret_cast<float4*>(out);

    // --- Issue group B loads (rows 4..7) before draining group A stores ---
    float4 vb[4];
#pragma unroll
    for (int i = 0; i < 4; i++) {
        if (rep[4 + i] > 0) vb[i] = ldg_evict_last(srcv + (size_t)(row0 + 4 + i) * D_VEC4 + t);
    }

    // --- Store group A ---
#pragma unroll
    for (int i = 0; i < 4; i++) {
        float4* o = outv + (size_t)off[i] * D_VEC4 + t;
#pragma unroll 8
        for (int r = 0; r < rep[i]; r++) {
            stg_evict_first(o, va[i]);
            o += D_VEC4;
        }
    }

    // --- Store group B ---
#pragma unroll
    for (int i = 0; i < 4; i++) {
        float4* o = outv + (size_t)off[4 + i] * D_VEC4 + t;
#pragma unroll 8
        for (int r = 0; r < rep[4 + i]; r++) {
            stg_evict_first(o, vb[i]);
            o += D_VEC4;
        }
    }
}

extern "C" void kernel_launch(void* const* d_in, const int* in_sizes, int n_in,
                              void* d_out, int out_size) {
    const float* encoder_h;
    const int* repeats;
    if (in_sizes[0] == N_ROWS * D_ELEMS) {
        encoder_h = (const float*)d_in[0];
        repeats   = (const int*)d_in[1];
    } else {
        encoder_h = (const float*)d_in[1];
        repeats   = (const int*)d_in[0];
    }
    float* out = (float*)d_out;
    (void)n_in; (void)out_size;

    repeat_fused_kernel<<<NB_CTAS, 256>>>(encoder_h, repeats, out);
}